// round 15
// baseline (speedup 1.0000x reference)
#include <cuda_runtime.h>
#include <stdint.h>
#include <math.h>

// ---------------- problem constants ----------------
#define BZ    32
#define CH    19
#define NP    30
#define PS    200
#define S     (CH*NP)          // 570
#define T     (BZ*S)           // 18240
#define DM    200
#define DMP   208              // padded K for score GEMM (13 x 16)
#define LLM   4096
#define KC    4096
#define NCONV (BZ*25*S*8)      // 3,648,000
#define TPAD  18304            // 143 * 128
#define NOUT  (T*DM)           // 3,648,000
#define NCB   32               // KC/128 column blocks (candidate granularity)
#define NF    128              // padded freq count (101 real)

// ---------------- device scratch (bss, zero-init, no allocations) ----------------
__device__ float g_a[NCONV];
__device__ float g_b[NCONV];
__device__ float g_pe[NOUT];                     // [T x 200]
__device__ float g_pe2p[(size_t)TPAD * DMP];     // padded: rows>=T and cols>=200 stay 0
__device__ float g_wT[(size_t)DM * LLM];         // inp_w transposed [200 x 4096]
__device__ float g_cp[(size_t)KC * DMP];         // C' fp32 (TwoSum-accurate), cols>=200 zero
__device__ float g_off[KC];
__device__ double g_offd[KC];
__device__ float g_table[KC * DM];
__device__ float g_stats[BZ * 5 * 2];
__device__ float g_ct[NF * DMP];                 // cos table [128 x 208], pad zero
__device__ float g_st[NF * DMP];                 // sin table
__device__ float g_mag[(size_t)T * NF];          // |rfft|/200, cols>=101 zero
__device__ float g_swp[DM * NF];                 // spec_w padded [200 x 128]
__device__ unsigned long long g_cand[(size_t)TPAD * NCB * 2];
__device__ int g_idx[T];

// ---------------- f32x2 helpers ----------------
__device__ __forceinline__ unsigned long long dupf2(float a) {
    unsigned long long d;
    unsigned int au = __float_as_uint(a);
    asm("mov.b64 %0, {%1,%2};" : "=l"(d) : "r"(au), "r"(au));
    return d;
}
__device__ __forceinline__ void fmaf2(unsigned long long& d, unsigned long long a,
                                      unsigned long long b) {
    asm("fma.rn.f32x2 %0, %1, %2, %0;" : "+l"(d) : "l"(a), "l"(b));
}
__device__ __forceinline__ float2 unpkf2(unsigned long long v) {
    union { unsigned long long u; float2 f; } cv;
    cv.u = v;
    return cv.f;
}
// TwoSum double-float accumulate (no muls -> contraction-safe)
__device__ __forceinline__ void dfacc(float& hi, float& lo, float f) {
    float s = hi + f;
    float z = s - hi;
    float err = (hi - (s - z)) + (f - z);
    lo += err;
    hi = s;
}

// ---------------- smem-tiled conv1: 8 token-rows per block, k=49, stride 25, pad 24 ---------
__global__ void __launch_bounds__(256)
conv1_kernel(const float* __restrict__ x, const float* __restrict__ w,
             const float* __restrict__ bias, float* __restrict__ out)
{
    __shared__ float xs[8][PS];
    __shared__ float ws[25 * 49];
    __shared__ float bs[25];
    int tid = threadIdx.x;
    int row0 = blockIdx.x * 8;

    for (int i = tid; i < 8 * PS; i += 256) {
        int r = i / PS, n = i % PS;
        xs[r][n] = x[(size_t)(row0 + r) * PS + n];
    }
    for (int i = tid; i < 25 * 49; i += 256) ws[i] = w[i];
    if (tid < 25) bs[tid] = bias[tid];
    __syncthreads();

    if (tid < 200) {
        int c = tid >> 3, wo = tid & 7;
        const float* wr = &ws[c * 49];
        int base = wo * 25 - 24;
        int t0 = (wo == 0) ? 24 : 0;          // only wo=0 clips (base=-24)
        #pragma unroll
        for (int r = 0; r < 8; r++) {
            float acc = bs[c];
            for (int t = t0; t < 49; t++)
                acc = fmaf(xs[r][base + t], wr[t], acc);
            int row = row0 + r;
            int b = row / S, s = row % S;
            out[((size_t)(b*25 + c) * S + s) * 8 + wo] = acc;
        }
    }
}

// ---------------- GroupNorm stats (fp32 partials, fp64 tree): 160 groups of 22800 floats ----
__global__ void gn_stats_kernel(const float* __restrict__ buf, float* __restrict__ stats)
{
    int grp = blockIdx.x;                 // b*5 + g
    const float* p = buf + grp * 22800;
    float s = 0.f, ss = 0.f;
    for (int i = threadIdx.x; i < 22800; i += 256) {
        float v = p[i]; s += v; ss = fmaf(v, v, ss);
    }
    __shared__ double rs[256], rss[256];
    rs[threadIdx.x] = (double)s; rss[threadIdx.x] = (double)ss;
    __syncthreads();
    for (int o = 128; o; o >>= 1) {
        if (threadIdx.x < o) { rs[threadIdx.x] += rs[threadIdx.x+o]; rss[threadIdx.x] += rss[threadIdx.x+o]; }
        __syncthreads();
    }
    if (threadIdx.x == 0) {
        double mean = rs[0] * (1.0/22800.0);
        double var  = rss[0] * (1.0/22800.0) - mean*mean;
        stats[grp*2+0] = (float)mean;
        stats[grp*2+1] = (float)(1.0 / sqrt(var + 1e-5));
    }
}

// ---------------- fused GN+GELU+conv25 (k=(1,3), pad(0,1)), smem-tiled -----------------------
__global__ void __launch_bounds__(256)
conv25f_kernel(const float* __restrict__ in, const float* __restrict__ stats,
               const float* __restrict__ gs, const float* __restrict__ gb,
               const float* __restrict__ w, const float* __restrict__ bias,
               float* __restrict__ out)
{
    __shared__ float tin[25 * 38 * 8];     // [ch][sl][wo], 7600 floats
    __shared__ float ws[25 * 75];          // 1875
    __shared__ float bs[25];
    int b  = blockIdx.y;
    int s0 = blockIdx.x * 38;
    int tid = threadIdx.x;

    for (int i = tid; i < 7600; i += 256) {
        int ch  = i / 304;
        int rem = i % 304;                 // sl*8 + wo, contiguous in global too
        float raw = in[((size_t)(b*25 + ch) * S + s0) * 8 + rem];
        int grp = b*5 + ch/5;
        float mean = stats[grp*2+0], rstd = stats[grp*2+1];
        float v = (raw - mean) * rstd * gs[ch] + gb[ch];
        tin[i] = 0.5f * v * (1.0f + erff(v * 0.70710678118654752f));
    }
    for (int i = tid; i < 1875; i += 256) ws[i] = w[i];
    if (tid < 25) bs[tid] = bias[tid];
    __syncthreads();

    if (tid < 200) {
        int o = tid >> 3, wo = tid & 7;
        const float* wrow = &ws[o * 75];
        for (int sl0 = 0; sl0 < 38; sl0 += 2) {
            float a0 = bs[o], a1 = bs[o];
            #pragma unroll 5
            for (int i = 0; i < 25; i++) {
                float w0 = wrow[i*3+0], w1 = wrow[i*3+1], w2 = wrow[i*3+2];
                const float* q0 = &tin[i*304 + sl0*8 + wo];
                const float* q1 = q0 + 8;
                if (wo > 0) { a0 = fmaf(q0[-1], w0, a0); a1 = fmaf(q1[-1], w0, a1); }
                a0 = fmaf(q0[0], w1, a0); a1 = fmaf(q1[0], w1, a1);
                if (wo < 7) { a0 = fmaf(q0[1], w2, a0); a1 = fmaf(q1[1], w2, a1); }
            }
            size_t ob = ((size_t)(b*25 + o) * S + s0 + sl0) * 8 + wo;
            out[ob]     = a0;
            out[ob + 8] = a1;
        }
    }
}

// ---------------- trig tables: C/S[k,n] = cos/sin(2*pi*k*n/200), rows<101 only -------------
__global__ void trig_kernel(float* __restrict__ ct, float* __restrict__ st)
{
    int idx = blockIdx.x * blockDim.x + threadIdx.x;
    if (idx >= 101 * PS) return;
    int k = idx / PS, n = idx % PS;
    int m = (k * n) % PS;
    float sv, cv;
    sincospif((float)m * 0.01f, &sv, &cv);
    ct[k * DMP + n] = cv;
    st[k * DMP + n] = sv;
}

// ---------------- spec_w padded copy: swp[d,k] = spec_w[d,k] (k<101) ----------------
__global__ void swpad_kernel(const float* __restrict__ sw, float* __restrict__ swp)
{
    int idx = blockIdx.x * blockDim.x + threadIdx.x;
    if (idx >= DM * 101) return;
    int d = idx / 101, k = idx % 101;
    swp[d * NF + k] = sw[idx];
}

// ---------------- DFT as GEMM (f32x2): mag[r,k] = |x_row . (C_k, S_k)| * 0.005 --------------
__global__ void __launch_bounds__(256)
dft_kernel(const float* __restrict__ x, const float* __restrict__ ct,
           const float* __restrict__ st, float* __restrict__ mag)
{
    __shared__ float Xs[16][68];
    __shared__ float Cs[16][132];
    __shared__ float Ss[16][132];
    int t  = threadIdx.x;
    int tx = t & 31, ty = t >> 5;         // n: tx*4..+3, m: ty*8..+7
    int bm0 = blockIdx.x * 64;
    unsigned long long reP[8][2] = {}, imP[8][2] = {};
    for (int k0 = 0; k0 < PS; k0 += 16) {
        #pragma unroll
        for (int l = 0; l < 4; l++) {
            int e = t + 256*l;
            int row = e >> 4, kk = e & 15;
            int gk = k0 + kk;
            Xs[kk][row] = (gk < PS) ? x[(size_t)(bm0 + row) * PS + gk] : 0.f;
        }
        #pragma unroll
        for (int l = 0; l < 8; l++) {
            int e = t + 256*l;
            int row = e >> 4, kk = e & 15;
            Cs[kk][row] = ct[row * DMP + k0 + kk];
            Ss[kk][row] = st[row * DMP + k0 + kk];
        }
        __syncthreads();
        #pragma unroll
        for (int k = 0; k < 16; k++) {
            float a[8];
            #pragma unroll
            for (int j = 0; j < 8; j++) a[j] = Xs[k][ty*8+j];
            ulonglong2 cP = *(const ulonglong2*)&Cs[k][tx*4];
            ulonglong2 sP = *(const ulonglong2*)&Ss[k][tx*4];
            unsigned long long cp_[2] = {cP.x, cP.y}, sp_[2] = {sP.x, sP.y};
            #pragma unroll
            for (int j = 0; j < 8; j++) {
                unsigned long long aD = dupf2(a[j]);
                #pragma unroll
                for (int i = 0; i < 2; i++) {
                    fmaf2(reP[j][i], aD, cp_[i]);
                    fmaf2(imP[j][i], aD, sp_[i]);
                }
            }
        }
        __syncthreads();
    }
    #pragma unroll
    for (int j = 0; j < 8; j++) {
        int r = bm0 + ty*8 + j;
        #pragma unroll
        for (int i = 0; i < 2; i++) {
            float2 rr = unpkf2(reP[j][i]);
            float2 ii = unpkf2(imP[j][i]);
            int n = tx*4 + i*2;
            mag[(size_t)r * NF + n + 0] = sqrtf(rr.x*rr.x + ii.x*ii.x) * 0.005f;
            mag[(size_t)r * NF + n + 1] = sqrtf(rr.y*rr.y + ii.y*ii.y) * 0.005f;
        }
    }
}

// ---------------- spectral projection + fused GN3-apply/GELU on h3 + transpose add ----------
__global__ void __launch_bounds__(256)
specproj_kernel(const float* __restrict__ mag, const float* __restrict__ swp,
                const float* __restrict__ sb, const float* __restrict__ h3,
                const float* __restrict__ stats, const float* __restrict__ gs,
                const float* __restrict__ gb, float* __restrict__ pe)
{
    __shared__ float As[16][68];
    __shared__ float Bs[16][68];
    int t  = threadIdx.x;
    int tx = t & 15, ty = t >> 4;
    int bm0 = blockIdx.x * 64, bn0 = blockIdx.y * 64;
    float acc[4][4] = {};
    for (int k0 = 0; k0 < NF; k0 += 16) {
        #pragma unroll
        for (int l = 0; l < 4; l++) {
            int e = t + 256*l;
            int row = e >> 4, kk = e & 15;
            int gn = bn0 + row;
            As[kk][row] = mag[(size_t)(bm0 + row) * NF + k0 + kk];
            Bs[kk][row] = (gn < DM) ? swp[gn * NF + k0 + kk] : 0.f;
        }
        __syncthreads();
        #pragma unroll
        for (int k = 0; k < 16; k++) {
            float a[4], bb[4];
            #pragma unroll
            for (int j = 0; j < 4; j++) a[j]  = As[k][ty*4+j];
            #pragma unroll
            for (int i = 0; i < 4; i++) bb[i] = Bs[k][tx*4+i];
            #pragma unroll
            for (int j = 0; j < 4; j++)
                #pragma unroll
                for (int i = 0; i < 4; i++)
                    acc[j][i] = fmaf(a[j], bb[i], acc[j][i]);
        }
        __syncthreads();
    }
    #pragma unroll
    for (int j = 0; j < 4; j++) {
        int r = bm0 + ty*4 + j;
        int b = r / S, s = r % S;
        const float* h3b = h3 + ((size_t)b*25*S + s) * 8;
        #pragma unroll
        for (int i = 0; i < 4; i++) {
            int d = bn0 + tx*4 + i;
            if (d < DM) {
                int c = d >> 3, w = d & 7;
                int grp = b*5 + c/5;
                float mean = stats[grp*2+0], rstd = stats[grp*2+1];
                float v = (h3b[(size_t)c * S * 8 + w] - mean) * rstd * gs[c] + gb[c];
                float g = 0.5f * v * (1.0f + erff(v * 0.70710678118654752f));
                pe[(size_t)r * DM + d] = acc[j][i] + sb[d] + g;
            }
        }
    }
}

// ---------------- smem-tiled depthwise positional conv 19x7, pad (9,3), + residual ----------
__global__ void __launch_bounds__(256)
posconv_kernel(const float* __restrict__ pe, const float* __restrict__ pw,
               const float* __restrict__ pb, float* __restrict__ out)
{
    __shared__ float tile[S * 8];          // 570 sites x 8 d
    __shared__ float wts[133 * 8];
    int tid = threadIdx.x;
    int dg0 = blockIdx.x * 8;
    int b   = blockIdx.y;
    for (int i = tid; i < S * 8; i += 256) {
        int s = i >> 3, j = i & 7;
        tile[i] = pe[((size_t)b * S + s) * DM + dg0 + j];
    }
    for (int i = tid; i < 133 * 8; i += 256) {
        int tp = i >> 3, j = i & 7;
        wts[i] = pw[(dg0 + j) * 133 + tp];
    }
    __syncthreads();
    for (int i = tid; i < S * 8; i += 256) {
        int s = i >> 3, j = i & 7;
        int ci = s / NP, pi = s % NP;
        float acc = tile[i] + pb[dg0 + j];
        for (int kh = 0; kh < 19; kh++) {
            int ih = ci + kh - 9;
            if ((unsigned)ih >= (unsigned)CH) continue;
            int rbase = ih * NP;
            #pragma unroll
            for (int kw = 0; kw < 7; kw++) {
                int iw = pi + kw - 3;
                if ((unsigned)iw >= (unsigned)NP) continue;
                acc = fmaf(tile[(rbase + iw) * 8 + j], wts[(kh*7 + kw) * 8 + j], acc);
            }
        }
        out[((size_t)b * S + s) * DMP + dg0 + j] = acc;
    }
}

// ---------------- fused codebook GEMM: C' (TwoSum dfloat) AND table, one A pass -------------
__global__ void __launch_bounds__(256)
gemm_cb_kernel(const float* __restrict__ A, const float* __restrict__ B1,
               const float* __restrict__ B2, const float* __restrict__ bias2,
               float* __restrict__ Cf, float* __restrict__ Tb)
{
    __shared__ float As[16][68];
    __shared__ float B1s[16][68];
    __shared__ float B2s[16][68];
    int t  = threadIdx.x;
    int tx = t & 15, ty = t >> 4;
    int bm0 = blockIdx.x * 64, bn0 = blockIdx.y * 64;
    float hi[4][4] = {}, lo[4][4] = {};
    unsigned long long taccP[4][2] = {};
    for (int k0 = 0; k0 < LLM; k0 += 16) {
        #pragma unroll
        for (int l = 0; l < 4; l++) {
            int e = t + 256*l;
            int row = e >> 4, kk = e & 15;
            int gn = bn0 + row;
            As[kk][row]  = A[(size_t)(bm0 + row) * LLM + k0 + kk];
            B1s[kk][row] = (gn < DM) ? B1[(size_t)gn * LLM + k0 + kk] : 0.f;
            B2s[kk][row] = (gn < DM) ? B2[(size_t)gn * LLM + k0 + kk] : 0.f;
        }
        __syncthreads();
        unsigned long long faccP[4][2] = {};
        #pragma unroll
        for (int k = 0; k < 16; k++) {
            float a[4];
            #pragma unroll
            for (int j = 0; j < 4; j++) a[j] = As[k][ty*4+j];
            ulonglong2 b1P = *(const ulonglong2*)&B1s[k][tx*4];
            ulonglong2 b2P = *(const ulonglong2*)&B2s[k][tx*4];
            unsigned long long b1_[2] = {b1P.x, b1P.y}, b2_[2] = {b2P.x, b2P.y};
            #pragma unroll
            for (int j = 0; j < 4; j++) {
                unsigned long long aD = dupf2(a[j]);
                #pragma unroll
                for (int i = 0; i < 2; i++) {
                    fmaf2(faccP[j][i], aD, b1_[i]);
                    fmaf2(taccP[j][i], aD, b2_[i]);
                }
            }
        }
        #pragma unroll
        for (int j = 0; j < 4; j++)
            #pragma unroll
            for (int i = 0; i < 2; i++) {
                float2 f = unpkf2(faccP[j][i]);
                dfacc(hi[j][i*2+0], lo[j][i*2+0], f.x);
                dfacc(hi[j][i*2+1], lo[j][i*2+1], f.y);
            }
        __syncthreads();
    }
    #pragma unroll
    for (int j = 0; j < 4; j++) {
        int m = bm0 + ty*4 + j;
        #pragma unroll
        for (int i = 0; i < 2; i++) {
            float2 tv = unpkf2(taccP[j][i]);
            #pragma unroll
            for (int e = 0; e < 2; e++) {
                int n = bn0 + tx*4 + i*2 + e;
                if (n < DM) {
                    Cf[(size_t)m*DMP + n] = hi[j][i*2+e] + lo[j][i*2+e];
                    Tb[(size_t)m*DM + n] = (e ? tv.y : tv.x) + bias2[n];
                }
            }
        }
    }
}

// ---------------- transpose inp_w [LLM,DM] -> wT [DM,LLM] ----------------
__global__ void transpose_w_kernel(const float* __restrict__ w, float* __restrict__ wT)
{
    int idx = blockIdx.x * blockDim.x + threadIdx.x;
    if (idx >= LLM * DM) return;
    int l = idx / DM, d = idx % DM;
    wT[(size_t)d * LLM + l] = w[idx];
}

// ---------------- off_k = inp_b . c_k - 0.5*||c_k||^2 (fp32 partials, fp64 reduce) ----------
__global__ void off_kernel(const float* __restrict__ cb, const float* __restrict__ inp_b,
                           float* __restrict__ offf, double* __restrict__ offd)
{
    int k = blockIdx.x;
    const float* p = cb + (size_t)k * LLM;
    float s1 = 0.f, s2 = 0.f;
    #pragma unroll
    for (int it = 0; it < LLM/256; it++) {
        int i = threadIdx.x + it * 256;
        float v = p[i];
        s1 = fmaf(inp_b[i], v, s1);
        s2 = fmaf(v, v, s2);
    }
    __shared__ double r1[256], r2[256];
    r1[threadIdx.x] = (double)s1; r2[threadIdx.x] = (double)s2;
    __syncthreads();
    for (int o = 128; o; o >>= 1) {
        if (threadIdx.x < o) { r1[threadIdx.x] += r1[threadIdx.x+o]; r2[threadIdx.x] += r2[threadIdx.x+o]; }
        __syncthreads();
    }
    if (!threadIdx.x) {
        double v = r1[0] - 0.5 * r2[0];
        offf[k] = (float)v;
        offd[k] = v;
    }
}

// ---------------- dominant: score = pe2p @ C'^T + off (f32x2, row-paired acc, dup-B smem) ----
// A pairs (a_j,a_{j+1}) come free from float4 regs; B staged duplicated as u64 (b_i,b_i)
// in interleaved layout [i*16+tx] -> LDS.64 conflict-free. Zero dup-movs in inner loop.
__global__ void __launch_bounds__(256, 2)
score_kernel(const float* __restrict__ A, const float* __restrict__ B,
             const float* __restrict__ off, unsigned long long* __restrict__ cand)
{
    __shared__ float As[16][132];
    __shared__ unsigned long long Bs2[16][128];   // [k][(c&7)*16 + (c>>3)] = (b_c, b_c)
    int t  = threadIdx.x;
    int tx = t & 15, ty = t >> 4;
    int bm0 = blockIdx.x * 128, bn0 = blockIdx.y * 128;

    int lrow = t >> 2;             // 0..63
    int lk4  = (t & 3) * 4;        // 0,4,8,12
    const float* Ap = A + (size_t)(bm0 + lrow) * DMP + lk4;
    const float* Bp = B + (size_t)(bn0 + lrow) * DMP + lk4;
    float* Bs2f = (float*)Bs2;                    // row stride 256 floats
    int slot1 = ((lrow & 7) * 16 + (lrow >> 3)) * 2;      // col lrow
    int slot2 = slot1 + 16;                               // col lrow+64 (+8 u64 slots)

    unsigned long long accP[4][8] = {};           // [jp][i]: rows (ty*8+2jp, +2jp+1), col tx*8+i
    float4 pa0 = *(const float4*)(Ap);
    float4 pa1 = *(const float4*)(Ap + (size_t)64 * DMP);
    float4 pb0 = *(const float4*)(Bp);
    float4 pb1 = *(const float4*)(Bp + (size_t)64 * DMP);

    for (int k0 = 0; k0 < DMP; k0 += 16) {
        As[lk4+0][lrow]    = pa0.x; As[lk4+1][lrow]    = pa0.y; As[lk4+2][lrow]    = pa0.z; As[lk4+3][lrow]    = pa0.w;
        As[lk4+0][lrow+64] = pa1.x; As[lk4+1][lrow+64] = pa1.y; As[lk4+2][lrow+64] = pa1.z; As[lk4+3][lrow+64] = pa1.w;
        {
            float v0[4] = {pb0.x, pb0.y, pb0.z, pb0.w};
            float v1[4] = {pb1.x, pb1.y, pb1.z, pb1.w};
            #pragma unroll
            for (int q = 0; q < 4; q++) {
                float* rowp = Bs2f + (size_t)(lk4 + q) * 256;
                rowp[slot1 + 0] = v0[q]; rowp[slot1 + 1] = v0[q];
                rowp[slot2 + 0] = v1[q]; rowp[slot2 + 1] = v1[q];
            }
        }
        __syncthreads();
        if (k0 + 16 < DMP) {
            pa0 = *(const float4*)(Ap + k0 + 16);
            pa1 = *(const float4*)(Ap + (size_t)64*DMP + k0 + 16);
            pb0 = *(const float4*)(Bp + k0 + 16);
            pb1 = *(const float4*)(Bp + (size_t)64*DMP + k0 + 16);
        }
        #pragma unroll
        for (int k = 0; k < 16; k++) {
            union { float4 f; unsigned long long u[2]; } aq0, aq1;
            aq0.f = *(const float4*)&As[k][ty*8];
            aq1.f = *(const float4*)&As[k][ty*8+4];
            unsigned long long ap[4] = {aq0.u[0], aq0.u[1], aq1.u[0], aq1.u[1]};
            unsigned long long bq[8];
            #pragma unroll
            for (int i = 0; i < 8; i++) bq[i] = Bs2[k][i*16 + tx];
            #pragma unroll
            for (int jp = 0; jp < 4; jp++)
                #pragma unroll
                for (int i = 0; i < 8; i++)
                    fmaf2(accP[jp][i], ap[jp], bq[i]);
        }
        __syncthreads();
    }

    float cn[8];
    #pragma unroll
    for (int i = 0; i < 8; i++) cn[i] = off[bn0 + tx*8 + i];
    #pragma unroll
    for (int jp = 0; jp < 4; jp++) {
        float2 va[8];
        #pragma unroll
        for (int i = 0; i < 8; i++) va[i] = unpkf2(accP[jp][i]);
        #pragma unroll
        for (int e = 0; e < 2; e++) {
            int row = bm0 + ty*8 + jp*2 + e;
            unsigned long long p1 = 0ull, p2 = 0ull;
            #pragma unroll
            for (int i = 0; i < 8; i++) {
                float sc = (e ? va[i].y : va[i].x) + cn[i];
                int col = bn0 + tx*8 + i;
                unsigned int key = __float_as_uint(sc);
                key = (key & 0x80000000u) ? ~key : (key | 0x80000000u);
                unsigned long long p = ((unsigned long long)key << 32) | (unsigned int)(KC - 1 - col);
                if (p > p1) { p2 = p1; p1 = p; }
                else if (p > p2) { p2 = p; }
            }
            #pragma unroll
            for (int off2 = 8; off2; off2 >>= 1) {
                unsigned long long q1 = __shfl_xor_sync(0xffffffffu, p1, off2);
                unsigned long long q2 = __shfl_xor_sync(0xffffffffu, p2, off2);
                if (q1 > p1) { p2 = (p1 > q2) ? p1 : q2; p1 = q1; }
                else if (q1 > p2) { p2 = q1; }
            }
            if (tx == 0) {
                size_t base = ((size_t)row * NCB + blockIdx.y) * 2;
                cand[base + 0] = p1;
                cand[base + 1] = p2;
            }
        }
    }
}

// ---------------- refine: merge 64 candidates -> top-8, double-float rescore, argmax ---------
__global__ void refine8_kernel(const unsigned long long* __restrict__ cand,
                               const float* __restrict__ pe2p, const float* __restrict__ cpf,
                               const double* __restrict__ offd, int* __restrict__ gidx)
{
    int row  = blockIdx.x;                // 0..T-1
    int tid  = threadIdx.x;               // 256
    int lane = tid & 31, wid = tid >> 5;
    __shared__ int cidx[8];
    __shared__ double wsc[8];

    if (wid == 0) {
        unsigned long long v[2];
        const unsigned long long* pc = cand + (size_t)row * (NCB * 2);
        #pragma unroll
        for (int i = 0; i < 2; i++) v[i] = pc[lane + 32*i];
        #pragma unroll
        for (int r = 0; r < 8; r++) {
            unsigned long long m = v[0] > v[1] ? v[0] : v[1];
            #pragma unroll
            for (int off = 16; off; off >>= 1) {
                unsigned long long q = __shfl_xor_sync(0xffffffffu, m, off);
                if (q > m) m = q;
            }
            #pragma unroll
            for (int i = 0; i < 2; i++) if (v[i] == m) v[i] = 0ull;
            if (lane == 0) cidx[r] = KC - 1 - (int)(unsigned int)(m & 0xffffffffull);
        }
    }
    __syncthreads();

    int ci = cidx[wid];
    const float* crow = cpf + (size_t)ci * DMP;
    const float* prow = pe2p + (size_t)row * DMP;
    // compensated double-float dot (TwoProdFMA + TwoSum), ~1e-14 relative
    float hi = 0.f, lo = 0.f;
    for (int i = lane; i < DM; i += 32) {
        float a = prow[i], b = crow[i];
        float p = a * b;
        float perr = fmaf(a, b, -p);
        float s = hi + p;
        float z = s - hi;
        float serr = (hi - (s - z)) + (p - z);
        hi = s;
        lo += serr + perr;
    }
    double sd = (double)hi + (double)lo;
    #pragma unroll
    for (int off = 16; off; off >>= 1)
        sd += __shfl_xor_sync(0xffffffffu, sd, off);
    if (lane == 0) wsc[wid] = sd + offd[ci];
    __syncthreads();

    if (tid == 0) {
        double bs = wsc[0]; int bi = cidx[0];
        #pragma unroll
        for (int w = 1; w < 8; w++) {
            if (wsc[w] > bs || (wsc[w] == bs && cidx[w] < bi)) { bs = wsc[w]; bi = cidx[w]; }
        }
        gidx[row] = bi;
    }
}

// ---------------- gather: out[t,d] = table[idx_t, d] ----------------
__global__ void gather_kernel(const int* __restrict__ gidx,
                              const float* __restrict__ table, float* __restrict__ out)
{
    int idx = blockIdx.x * blockDim.x + threadIdx.x;
    if (idx >= NOUT) return;
    int t = idx / DM, d = idx % DM;
    int col = gidx[t];
    out[idx] = table[(size_t)col * DM + d];
}

// ---------------- host ----------------
extern "C" void kernel_launch(void* const* d_in, const int* in_sizes, int n_in,
                              void* d_out, int out_size)
{
    const float* x      = (const float*)d_in[0];
    const float* c1w    = (const float*)d_in[1];
    const float* c1b    = (const float*)d_in[2];
    const float* gn1s   = (const float*)d_in[3];
    const float* gn1b   = (const float*)d_in[4];
    const float* c2w    = (const float*)d_in[5];
    const float* c2b    = (const float*)d_in[6];
    const float* gn2s   = (const float*)d_in[7];
    const float* gn2b   = (const float*)d_in[8];
    const float* c3w    = (const float*)d_in[9];
    const float* c3b    = (const float*)d_in[10];
    const float* gn3s   = (const float*)d_in[11];
    const float* gn3b   = (const float*)d_in[12];
    const float* spec_w = (const float*)d_in[13];
    const float* spec_b = (const float*)d_in[14];
    const float* pos_w  = (const float*)d_in[15];
    const float* pos_b  = (const float*)d_in[16];
    const float* inp_w  = (const float*)d_in[17];
    const float* inp_b  = (const float*)d_in[18];
    const float* cb     = (const float*)d_in[19];
    const float* outp_w = (const float*)d_in[20];
    const float* outp_b = (const float*)d_in[21];
    float* out = (float*)d_out;

    float *pa, *pb, *ppe, *ppe2p, *pwT, *pcp, *poff, *ptable, *pstats;
    float *pct, *pst, *pmag, *pswp;
    double *poffd;
    unsigned long long* pcand;
    int* pidx;
    cudaGetSymbolAddress((void**)&pa,     g_a);
    cudaGetSymbolAddress((void**)&pb,     g_b);
    cudaGetSymbolAddress((void**)&ppe,    g_pe);
    cudaGetSymbolAddress((void**)&ppe2p,  g_pe2p);
    cudaGetSymbolAddress((void**)&pwT,    g_wT);
    cudaGetSymbolAddress((void**)&pcp,    g_cp);
    cudaGetSymbolAddress((void**)&poff,   g_off);
    cudaGetSymbolAddress((void**)&poffd,  g_offd);
    cudaGetSymbolAddress((void**)&ptable, g_table);
    cudaGetSymbolAddress((void**)&pstats, g_stats);
    cudaGetSymbolAddress((void**)&pct,    g_ct);
    cudaGetSymbolAddress((void**)&pst,    g_st);
    cudaGetSymbolAddress((void**)&pmag,   g_mag);
    cudaGetSymbolAddress((void**)&pswp,   g_swp);
    cudaGetSymbolAddress((void**)&pcand,  g_cand);
    cudaGetSymbolAddress((void**)&pidx,   g_idx);

    // side streams + events: created once on the (uncaptured) correctness call,
    // reused by the capture call. Work sequence is identical on every call.
    static cudaStream_t s_side = 0, s_spec = 0;
    static cudaEvent_t  s_fork = 0, s_join = 0, s_fork2 = 0, s_join2 = 0;
    if (s_side == 0) {
        cudaStreamCreateWithFlags(&s_side, cudaStreamNonBlocking);
        cudaStreamCreateWithFlags(&s_spec, cudaStreamNonBlocking);
        cudaEventCreateWithFlags(&s_fork,  cudaEventDisableTiming);
        cudaEventCreateWithFlags(&s_join,  cudaEventDisableTiming);
        cudaEventCreateWithFlags(&s_fork2, cudaEventDisableTiming);
        cudaEventCreateWithFlags(&s_join2, cudaEventDisableTiming);
    }

    // ---- fork 1: codebook branch on side stream (independent of encoder) ----
    cudaEventRecord(s_fork, 0);
    cudaStreamWaitEvent(s_side, s_fork, 0);
    transpose_w_kernel<<<(LLM*DM + 255)/256, 256, 0, s_side>>>(inp_w, pwT);
    {
        dim3 grid(KC/64, (DM + 63)/64);
        gemm_cb_kernel<<<grid, 256, 0, s_side>>>(cb, pwT, outp_w, outp_b, pcp, ptable);
    }
    off_kernel<<<KC, 256, 0, s_side>>>(cb, inp_b, poff, poffd);
    cudaEventRecord(s_join, s_side);

    // ---- fork 2: spectral pre-chain on its own stream (depends only on x) ----
    cudaEventRecord(s_fork2, 0);
    cudaStreamWaitEvent(s_spec, s_fork2, 0);
    trig_kernel<<<(101*PS + 255)/256, 256, 0, s_spec>>>(pct, pst);
    swpad_kernel<<<(DM*101 + 255)/256, 256, 0, s_spec>>>(spec_w, pswp);
    dft_kernel<<<T/64, 256, 0, s_spec>>>(x, pct, pst, pmag);
    cudaEventRecord(s_join2, s_spec);

    // ---- main: encoder chain (GN-apply fused into conv25f / specproj) ----
    conv1_kernel<<<T/8, 256>>>(x, c1w, c1b, pa);
    gn_stats_kernel<<<160, 256>>>(pa, pstats);
    {
        dim3 grid(15, BZ);
        conv25f_kernel<<<grid, 256>>>(pa, pstats, gn1s, gn1b, c2w, c2b, pb);
    }
    gn_stats_kernel<<<160, 256>>>(pb, pstats);
    {
        dim3 grid(15, BZ);
        conv25f_kernel<<<grid, 256>>>(pb, pstats, gn2s, gn2b, c3w, c3b, pa);
    }
    gn_stats_kernel<<<160, 256>>>(pa, pstats);

    // join spectral pre-chain, then fused projection
    cudaStreamWaitEvent(0, s_join2, 0);
    {
        dim3 grid(T/64, (DM + 63)/64);
        specproj_kernel<<<grid, 256>>>(pmag, pswp, spec_b, pa, pstats, gn3s, gn3b, ppe);
    }

    // smem-tiled positional conv (writes padded [TPAD x 208])
    {
        dim3 grid(25, BZ);
        posconv_kernel<<<grid, 256>>>(ppe, pos_w, pos_b, ppe2p);
    }

    // ---- join 1: score needs pcp/poff from side stream ----
    cudaStreamWaitEvent(0, s_join, 0);

    // score GEMM [TPAD x 4096], K=208, fused top-2 per 128-block
    {
        dim3 grid(TPAD/128, KC/128);
        score_kernel<<<grid, 256>>>(ppe2p, pcp, poff, pcand);
    }

    // exact decision: top-8 of 64 candidates, double-float rescore, argmax (tie -> smaller)
    refine8_kernel<<<T, 256>>>(pcand, ppe2p, pcp, poffd, pidx);

    // gather quantized output
    gather_kernel<<<(NOUT + 255)/256, 256>>>(pidx, ptable, out);
}

// round 16
// speedup vs baseline: 1.2725x; 1.2725x over previous
#include <cuda_runtime.h>
#include <stdint.h>
#include <math.h>

// ---------------- problem constants ----------------
#define BZ    32
#define CH    19
#define NP    30
#define PS    200
#define S     (CH*NP)          // 570
#define T     (BZ*S)           // 18240
#define DM    200
#define DMP   208              // padded K for score GEMM (13 x 16)
#define LLM   4096
#define KC    4096
#define NCONV (BZ*25*S*8)      // 3,648,000
#define TPAD  18304            // 143 * 128
#define NOUT  (T*DM)           // 3,648,000
#define NCB   32               // KC/128 column blocks (candidate granularity)
#define NF    128              // padded freq count (101 real)

// ---------------- device scratch (bss, zero-init, no allocations) ----------------
__device__ float g_a[NCONV];
__device__ float g_b[NCONV];
__device__ float g_pe[NOUT];                     // [T x 200]
__device__ float g_pe2p[(size_t)TPAD * DMP];     // padded: rows>=T and cols>=200 stay 0
__device__ float g_wT[(size_t)DM * LLM];         // inp_w transposed [200 x 4096]
__device__ float g_cp[(size_t)KC * DMP];         // C' fp32 (TwoSum-accurate), cols>=200 zero
__device__ float g_off[KC];
__device__ double g_offd[KC];
__device__ float g_table[KC * DM];
__device__ float g_stats[BZ * 5 * 2];
__device__ float g_ct[NF * DMP];                 // cos table [128 x 208], pad zero
__device__ float g_st[NF * DMP];                 // sin table
__device__ float g_mag[(size_t)T * NF];          // |rfft|/200, cols>=101 zero
__device__ float g_swp[DM * NF];                 // spec_w padded [200 x 128]
__device__ unsigned long long g_cand[(size_t)TPAD * NCB * 2];
__device__ int g_idx[T];

// ---------------- f32x2 helpers ----------------
__device__ __forceinline__ unsigned long long dupf2(float a) {
    unsigned long long d;
    unsigned int au = __float_as_uint(a);
    asm("mov.b64 %0, {%1,%2};" : "=l"(d) : "r"(au), "r"(au));
    return d;
}
__device__ __forceinline__ void fmaf2(unsigned long long& d, unsigned long long a,
                                      unsigned long long b) {
    asm("fma.rn.f32x2 %0, %1, %2, %0;" : "+l"(d) : "l"(a), "l"(b));
}
__device__ __forceinline__ float2 unpkf2(unsigned long long v) {
    union { unsigned long long u; float2 f; } cv;
    cv.u = v;
    return cv.f;
}
// TwoSum double-float accumulate (no muls -> contraction-safe)
__device__ __forceinline__ void dfacc(float& hi, float& lo, float f) {
    float s = hi + f;
    float z = s - hi;
    float err = (hi - (s - z)) + (f - z);
    lo += err;
    hi = s;
}

// ---------------- smem-tiled conv1: 8 token-rows per block, k=49, stride 25, pad 24 ---------
__global__ void __launch_bounds__(256)
conv1_kernel(const float* __restrict__ x, const float* __restrict__ w,
             const float* __restrict__ bias, float* __restrict__ out)
{
    __shared__ float xs[8][PS];
    __shared__ float ws[25 * 49];
    __shared__ float bs[25];
    int tid = threadIdx.x;
    int row0 = blockIdx.x * 8;

    for (int i = tid; i < 8 * PS; i += 256) {
        int r = i / PS, n = i % PS;
        xs[r][n] = x[(size_t)(row0 + r) * PS + n];
    }
    for (int i = tid; i < 25 * 49; i += 256) ws[i] = w[i];
    if (tid < 25) bs[tid] = bias[tid];
    __syncthreads();

    if (tid < 200) {
        int c = tid >> 3, wo = tid & 7;
        const float* wr = &ws[c * 49];
        int base = wo * 25 - 24;
        int t0 = (wo == 0) ? 24 : 0;          // only wo=0 clips (base=-24)
        #pragma unroll
        for (int r = 0; r < 8; r++) {
            float acc = bs[c];
            for (int t = t0; t < 49; t++)
                acc = fmaf(xs[r][base + t], wr[t], acc);
            int row = row0 + r;
            int b = row / S, s = row % S;
            out[((size_t)(b*25 + c) * S + s) * 8 + wo] = acc;
        }
    }
}

// ---------------- GroupNorm stats (fp32 partials, fp64 tree): 160 groups of 22800 floats ----
__global__ void gn_stats_kernel(const float* __restrict__ buf, float* __restrict__ stats)
{
    int grp = blockIdx.x;                 // b*5 + g
    const float* p = buf + grp * 22800;
    float s = 0.f, ss = 0.f;
    for (int i = threadIdx.x; i < 22800; i += 256) {
        float v = p[i]; s += v; ss = fmaf(v, v, ss);
    }
    __shared__ double rs[256], rss[256];
    rs[threadIdx.x] = (double)s; rss[threadIdx.x] = (double)ss;
    __syncthreads();
    for (int o = 128; o; o >>= 1) {
        if (threadIdx.x < o) { rs[threadIdx.x] += rs[threadIdx.x+o]; rss[threadIdx.x] += rss[threadIdx.x+o]; }
        __syncthreads();
    }
    if (threadIdx.x == 0) {
        double mean = rs[0] * (1.0/22800.0);
        double var  = rss[0] * (1.0/22800.0) - mean*mean;
        stats[grp*2+0] = (float)mean;
        stats[grp*2+1] = (float)(1.0 / sqrt(var + 1e-5));
    }
}

// ---------------- fused GN+GELU+conv25 (k=(1,3), pad(0,1)), smem-tiled -----------------------
__global__ void __launch_bounds__(256)
conv25f_kernel(const float* __restrict__ in, const float* __restrict__ stats,
               const float* __restrict__ gs, const float* __restrict__ gb,
               const float* __restrict__ w, const float* __restrict__ bias,
               float* __restrict__ out)
{
    __shared__ float tin[25 * 38 * 8];     // [ch][sl][wo], 7600 floats
    __shared__ float ws[25 * 75];          // 1875
    __shared__ float bs[25];
    int b  = blockIdx.y;
    int s0 = blockIdx.x * 38;
    int tid = threadIdx.x;

    for (int i = tid; i < 7600; i += 256) {
        int ch  = i / 304;
        int rem = i % 304;                 // sl*8 + wo, contiguous in global too
        float raw = in[((size_t)(b*25 + ch) * S + s0) * 8 + rem];
        int grp = b*5 + ch/5;
        float mean = stats[grp*2+0], rstd = stats[grp*2+1];
        float v = (raw - mean) * rstd * gs[ch] + gb[ch];
        tin[i] = 0.5f * v * (1.0f + erff(v * 0.70710678118654752f));
    }
    for (int i = tid; i < 1875; i += 256) ws[i] = w[i];
    if (tid < 25) bs[tid] = bias[tid];
    __syncthreads();

    if (tid < 200) {
        int o = tid >> 3, wo = tid & 7;
        const float* wrow = &ws[o * 75];
        for (int sl0 = 0; sl0 < 38; sl0 += 2) {
            float a0 = bs[o], a1 = bs[o];
            #pragma unroll 5
            for (int i = 0; i < 25; i++) {
                float w0 = wrow[i*3+0], w1 = wrow[i*3+1], w2 = wrow[i*3+2];
                const float* q0 = &tin[i*304 + sl0*8 + wo];
                const float* q1 = q0 + 8;
                if (wo > 0) { a0 = fmaf(q0[-1], w0, a0); a1 = fmaf(q1[-1], w0, a1); }
                a0 = fmaf(q0[0], w1, a0); a1 = fmaf(q1[0], w1, a1);
                if (wo < 7) { a0 = fmaf(q0[1], w2, a0); a1 = fmaf(q1[1], w2, a1); }
            }
            size_t ob = ((size_t)(b*25 + o) * S + s0 + sl0) * 8 + wo;
            out[ob]     = a0;
            out[ob + 8] = a1;
        }
    }
}

// ---------------- trig tables: C/S[k,n] = cos/sin(2*pi*k*n/200), rows<101 only -------------
__global__ void trig_kernel(float* __restrict__ ct, float* __restrict__ st)
{
    int idx = blockIdx.x * blockDim.x + threadIdx.x;
    if (idx >= 101 * PS) return;
    int k = idx / PS, n = idx % PS;
    int m = (k * n) % PS;
    float sv, cv;
    sincospif((float)m * 0.01f, &sv, &cv);
    ct[k * DMP + n] = cv;
    st[k * DMP + n] = sv;
}

// ---------------- spec_w padded copy: swp[d,k] = spec_w[d,k] (k<101) ----------------
__global__ void swpad_kernel(const float* __restrict__ sw, float* __restrict__ swp)
{
    int idx = blockIdx.x * blockDim.x + threadIdx.x;
    if (idx >= DM * 101) return;
    int d = idx / 101, k = idx % 101;
    swp[d * NF + k] = sw[idx];
}

// ---------------- DFT as GEMM (f32x2): mag[r,k] = |x_row . (C_k, S_k)| * 0.005 --------------
__global__ void __launch_bounds__(256)
dft_kernel(const float* __restrict__ x, const float* __restrict__ ct,
           const float* __restrict__ st, float* __restrict__ mag)
{
    __shared__ float Xs[16][68];
    __shared__ float Cs[16][132];
    __shared__ float Ss[16][132];
    int t  = threadIdx.x;
    int tx = t & 31, ty = t >> 5;         // n: tx*4..+3, m: ty*8..+7
    int bm0 = blockIdx.x * 64;
    unsigned long long reP[8][2] = {}, imP[8][2] = {};
    for (int k0 = 0; k0 < PS; k0 += 16) {
        #pragma unroll
        for (int l = 0; l < 4; l++) {
            int e = t + 256*l;
            int row = e >> 4, kk = e & 15;
            int gk = k0 + kk;
            Xs[kk][row] = (gk < PS) ? x[(size_t)(bm0 + row) * PS + gk] : 0.f;
        }
        #pragma unroll
        for (int l = 0; l < 8; l++) {
            int e = t + 256*l;
            int row = e >> 4, kk = e & 15;
            Cs[kk][row] = ct[row * DMP + k0 + kk];
            Ss[kk][row] = st[row * DMP + k0 + kk];
        }
        __syncthreads();
        #pragma unroll
        for (int k = 0; k < 16; k++) {
            float a[8];
            #pragma unroll
            for (int j = 0; j < 8; j++) a[j] = Xs[k][ty*8+j];
            ulonglong2 cP = *(const ulonglong2*)&Cs[k][tx*4];
            ulonglong2 sP = *(const ulonglong2*)&Ss[k][tx*4];
            unsigned long long cp_[2] = {cP.x, cP.y}, sp_[2] = {sP.x, sP.y};
            #pragma unroll
            for (int j = 0; j < 8; j++) {
                unsigned long long aD = dupf2(a[j]);
                #pragma unroll
                for (int i = 0; i < 2; i++) {
                    fmaf2(reP[j][i], aD, cp_[i]);
                    fmaf2(imP[j][i], aD, sp_[i]);
                }
            }
        }
        __syncthreads();
    }
    #pragma unroll
    for (int j = 0; j < 8; j++) {
        int r = bm0 + ty*8 + j;
        #pragma unroll
        for (int i = 0; i < 2; i++) {
            float2 rr = unpkf2(reP[j][i]);
            float2 ii = unpkf2(imP[j][i]);
            int n = tx*4 + i*2;
            mag[(size_t)r * NF + n + 0] = sqrtf(rr.x*rr.x + ii.x*ii.x) * 0.005f;
            mag[(size_t)r * NF + n + 1] = sqrtf(rr.y*rr.y + ii.y*ii.y) * 0.005f;
        }
    }
}

// ---------------- spectral projection + fused GN3-apply/GELU on h3 + transpose add ----------
__global__ void __launch_bounds__(256)
specproj_kernel(const float* __restrict__ mag, const float* __restrict__ swp,
                const float* __restrict__ sb, const float* __restrict__ h3,
                const float* __restrict__ stats, const float* __restrict__ gs,
                const float* __restrict__ gb, float* __restrict__ pe)
{
    __shared__ float As[16][68];
    __shared__ float Bs[16][68];
    int t  = threadIdx.x;
    int tx = t & 15, ty = t >> 4;
    int bm0 = blockIdx.x * 64, bn0 = blockIdx.y * 64;
    float acc[4][4] = {};
    for (int k0 = 0; k0 < NF; k0 += 16) {
        #pragma unroll
        for (int l = 0; l < 4; l++) {
            int e = t + 256*l;
            int row = e >> 4, kk = e & 15;
            int gn = bn0 + row;
            As[kk][row] = mag[(size_t)(bm0 + row) * NF + k0 + kk];
            Bs[kk][row] = (gn < DM) ? swp[gn * NF + k0 + kk] : 0.f;
        }
        __syncthreads();
        #pragma unroll
        for (int k = 0; k < 16; k++) {
            float a[4], bb[4];
            #pragma unroll
            for (int j = 0; j < 4; j++) a[j]  = As[k][ty*4+j];
            #pragma unroll
            for (int i = 0; i < 4; i++) bb[i] = Bs[k][tx*4+i];
            #pragma unroll
            for (int j = 0; j < 4; j++)
                #pragma unroll
                for (int i = 0; i < 4; i++)
                    acc[j][i] = fmaf(a[j], bb[i], acc[j][i]);
        }
        __syncthreads();
    }
    #pragma unroll
    for (int j = 0; j < 4; j++) {
        int r = bm0 + ty*4 + j;
        int b = r / S, s = r % S;
        const float* h3b = h3 + ((size_t)b*25*S + s) * 8;
        #pragma unroll
        for (int i = 0; i < 4; i++) {
            int d = bn0 + tx*4 + i;
            if (d < DM) {
                int c = d >> 3, w = d & 7;
                int grp = b*5 + c/5;
                float mean = stats[grp*2+0], rstd = stats[grp*2+1];
                float v = (h3b[(size_t)c * S * 8 + w] - mean) * rstd * gs[c] + gb[c];
                float g = 0.5f * v * (1.0f + erff(v * 0.70710678118654752f));
                pe[(size_t)r * DM + d] = acc[j][i] + sb[d] + g;
            }
        }
    }
}

// ---------------- smem-tiled depthwise positional conv 19x7, pad (9,3), + residual ----------
__global__ void __launch_bounds__(256)
posconv_kernel(const float* __restrict__ pe, const float* __restrict__ pw,
               const float* __restrict__ pb, float* __restrict__ out)
{
    __shared__ float tile[S * 8];          // 570 sites x 8 d
    __shared__ float wts[133 * 8];
    int tid = threadIdx.x;
    int dg0 = blockIdx.x * 8;
    int b   = blockIdx.y;
    for (int i = tid; i < S * 8; i += 256) {
        int s = i >> 3, j = i & 7;
        tile[i] = pe[((size_t)b * S + s) * DM + dg0 + j];
    }
    for (int i = tid; i < 133 * 8; i += 256) {
        int tp = i >> 3, j = i & 7;
        wts[i] = pw[(dg0 + j) * 133 + tp];
    }
    __syncthreads();
    for (int i = tid; i < S * 8; i += 256) {
        int s = i >> 3, j = i & 7;
        int ci = s / NP, pi = s % NP;
        float acc = tile[i] + pb[dg0 + j];
        for (int kh = 0; kh < 19; kh++) {
            int ih = ci + kh - 9;
            if ((unsigned)ih >= (unsigned)CH) continue;
            int rbase = ih * NP;
            #pragma unroll
            for (int kw = 0; kw < 7; kw++) {
                int iw = pi + kw - 3;
                if ((unsigned)iw >= (unsigned)NP) continue;
                acc = fmaf(tile[(rbase + iw) * 8 + j], wts[(kh*7 + kw) * 8 + j], acc);
            }
        }
        out[((size_t)b * S + s) * DMP + dg0 + j] = acc;
    }
}

// ---------------- fused codebook GEMM: C' (TwoSum dfloat) AND table, one A pass -------------
__global__ void __launch_bounds__(256)
gemm_cb_kernel(const float* __restrict__ A, const float* __restrict__ B1,
               const float* __restrict__ B2, const float* __restrict__ bias2,
               float* __restrict__ Cf, float* __restrict__ Tb)
{
    __shared__ float As[16][68];
    __shared__ float B1s[16][68];
    __shared__ float B2s[16][68];
    int t  = threadIdx.x;
    int tx = t & 15, ty = t >> 4;
    int bm0 = blockIdx.x * 64, bn0 = blockIdx.y * 64;
    float hi[4][4] = {}, lo[4][4] = {};
    unsigned long long taccP[4][2] = {};
    for (int k0 = 0; k0 < LLM; k0 += 16) {
        #pragma unroll
        for (int l = 0; l < 4; l++) {
            int e = t + 256*l;
            int row = e >> 4, kk = e & 15;
            int gn = bn0 + row;
            As[kk][row]  = A[(size_t)(bm0 + row) * LLM + k0 + kk];
            B1s[kk][row] = (gn < DM) ? B1[(size_t)gn * LLM + k0 + kk] : 0.f;
            B2s[kk][row] = (gn < DM) ? B2[(size_t)gn * LLM + k0 + kk] : 0.f;
        }
        __syncthreads();
        unsigned long long faccP[4][2] = {};
        #pragma unroll
        for (int k = 0; k < 16; k++) {
            float a[4];
            #pragma unroll
            for (int j = 0; j < 4; j++) a[j] = As[k][ty*4+j];
            ulonglong2 b1P = *(const ulonglong2*)&B1s[k][tx*4];
            ulonglong2 b2P = *(const ulonglong2*)&B2s[k][tx*4];
            unsigned long long b1_[2] = {b1P.x, b1P.y}, b2_[2] = {b2P.x, b2P.y};
            #pragma unroll
            for (int j = 0; j < 4; j++) {
                unsigned long long aD = dupf2(a[j]);
                #pragma unroll
                for (int i = 0; i < 2; i++) {
                    fmaf2(faccP[j][i], aD, b1_[i]);
                    fmaf2(taccP[j][i], aD, b2_[i]);
                }
            }
        }
        #pragma unroll
        for (int j = 0; j < 4; j++)
            #pragma unroll
            for (int i = 0; i < 2; i++) {
                float2 f = unpkf2(faccP[j][i]);
                dfacc(hi[j][i*2+0], lo[j][i*2+0], f.x);
                dfacc(hi[j][i*2+1], lo[j][i*2+1], f.y);
            }
        __syncthreads();
    }
    #pragma unroll
    for (int j = 0; j < 4; j++) {
        int m = bm0 + ty*4 + j;
        #pragma unroll
        for (int i = 0; i < 2; i++) {
            float2 tv = unpkf2(taccP[j][i]);
            #pragma unroll
            for (int e = 0; e < 2; e++) {
                int n = bn0 + tx*4 + i*2 + e;
                if (n < DM) {
                    Cf[(size_t)m*DMP + n] = hi[j][i*2+e] + lo[j][i*2+e];
                    Tb[(size_t)m*DM + n] = (e ? tv.y : tv.x) + bias2[n];
                }
            }
        }
    }
}

// ---------------- transpose inp_w [LLM,DM] -> wT [DM,LLM] ----------------
__global__ void transpose_w_kernel(const float* __restrict__ w, float* __restrict__ wT)
{
    int idx = blockIdx.x * blockDim.x + threadIdx.x;
    if (idx >= LLM * DM) return;
    int l = idx / DM, d = idx % DM;
    wT[(size_t)d * LLM + l] = w[idx];
}

// ---------------- off_k = inp_b . c_k - 0.5*||c_k||^2 (fp32 partials, fp64 reduce) ----------
__global__ void off_kernel(const float* __restrict__ cb, const float* __restrict__ inp_b,
                           float* __restrict__ offf, double* __restrict__ offd)
{
    int k = blockIdx.x;
    const float* p = cb + (size_t)k * LLM;
    float s1 = 0.f, s2 = 0.f;
    #pragma unroll
    for (int it = 0; it < LLM/256; it++) {
        int i = threadIdx.x + it * 256;
        float v = p[i];
        s1 = fmaf(inp_b[i], v, s1);
        s2 = fmaf(v, v, s2);
    }
    __shared__ double r1[256], r2[256];
    r1[threadIdx.x] = (double)s1; r2[threadIdx.x] = (double)s2;
    __syncthreads();
    for (int o = 128; o; o >>= 1) {
        if (threadIdx.x < o) { r1[threadIdx.x] += r1[threadIdx.x+o]; r2[threadIdx.x] += r2[threadIdx.x+o]; }
        __syncthreads();
    }
    if (!threadIdx.x) {
        double v = r1[0] - 0.5 * r2[0];
        offf[k] = (float)v;
        offd[k] = v;
    }
}

// ---------------- dominant: score = pe2p @ C'^T + off (f32x2), top-2 per 128-block ----------
// (round-14 proven version)
__global__ void __launch_bounds__(256, 2)
score_kernel(const float* __restrict__ A, const float* __restrict__ B,
             const float* __restrict__ off, unsigned long long* __restrict__ cand)
{
    __shared__ float As[16][132];
    __shared__ float Bs[16][132];
    int t  = threadIdx.x;
    int tx = t & 15, ty = t >> 4;
    int bm0 = blockIdx.x * 128, bn0 = blockIdx.y * 128;

    int lrow = t >> 2;             // 0..63
    int lk4  = (t & 3) * 4;        // 0,4,8,12
    const float* Ap = A + (size_t)(bm0 + lrow) * DMP + lk4;
    const float* Bp = B + (size_t)(bn0 + lrow) * DMP + lk4;

    unsigned long long accP[8][4] = {};
    float4 pa0 = *(const float4*)(Ap);
    float4 pa1 = *(const float4*)(Ap + (size_t)64 * DMP);
    float4 pb0 = *(const float4*)(Bp);
    float4 pb1 = *(const float4*)(Bp + (size_t)64 * DMP);

    for (int k0 = 0; k0 < DMP; k0 += 16) {
        As[lk4+0][lrow]    = pa0.x; As[lk4+1][lrow]    = pa0.y; As[lk4+2][lrow]    = pa0.z; As[lk4+3][lrow]    = pa0.w;
        As[lk4+0][lrow+64] = pa1.x; As[lk4+1][lrow+64] = pa1.y; As[lk4+2][lrow+64] = pa1.z; As[lk4+3][lrow+64] = pa1.w;
        Bs[lk4+0][lrow]    = pb0.x; Bs[lk4+1][lrow]    = pb0.y; Bs[lk4+2][lrow]    = pb0.z; Bs[lk4+3][lrow]    = pb0.w;
        Bs[lk4+0][lrow+64] = pb1.x; Bs[lk4+1][lrow+64] = pb1.y; Bs[lk4+2][lrow+64] = pb1.z; Bs[lk4+3][lrow+64] = pb1.w;
        __syncthreads();
        if (k0 + 16 < DMP) {
            pa0 = *(const float4*)(Ap + k0 + 16);
            pa1 = *(const float4*)(Ap + (size_t)64*DMP + k0 + 16);
            pb0 = *(const float4*)(Bp + k0 + 16);
            pb1 = *(const float4*)(Bp + (size_t)64*DMP + k0 + 16);
        }
        #pragma unroll
        for (int k = 0; k < 16; k++) {
            float a[8];
            *(float4*)&a[0] = *(const float4*)&As[k][ty*8];
            *(float4*)&a[4] = *(const float4*)&As[k][ty*8+4];
            ulonglong2 bA = *(const ulonglong2*)&Bs[k][tx*8];
            ulonglong2 bB = *(const ulonglong2*)&Bs[k][tx*8+4];
            unsigned long long bP[4] = {bA.x, bA.y, bB.x, bB.y};
            #pragma unroll
            for (int j = 0; j < 8; j++) {
                unsigned long long aD = dupf2(a[j]);
                #pragma unroll
                for (int i = 0; i < 4; i++)
                    fmaf2(accP[j][i], aD, bP[i]);
            }
        }
        __syncthreads();
    }

    float cn[8];
    #pragma unroll
    for (int i = 0; i < 8; i++) cn[i] = off[bn0 + tx*8 + i];
    #pragma unroll
    for (int j = 0; j < 8; j++) {
        int row = bm0 + ty*8 + j;
        unsigned long long p1 = 0ull, p2 = 0ull;
        #pragma unroll
        for (int i = 0; i < 4; i++) {
            float2 av = unpkf2(accP[j][i]);
            #pragma unroll
            for (int e = 0; e < 2; e++) {
                float sc = (e ? av.y : av.x) + cn[i*2+e];
                int col = bn0 + tx*8 + i*2 + e;
                unsigned int key = __float_as_uint(sc);
                key = (key & 0x80000000u) ? ~key : (key | 0x80000000u);
                unsigned long long p = ((unsigned long long)key << 32) | (unsigned int)(KC - 1 - col);
                if (p > p1) { p2 = p1; p1 = p; }
                else if (p > p2) { p2 = p; }
            }
        }
        #pragma unroll
        for (int off2 = 8; off2; off2 >>= 1) {
            unsigned long long q1 = __shfl_xor_sync(0xffffffffu, p1, off2);
            unsigned long long q2 = __shfl_xor_sync(0xffffffffu, p2, off2);
            if (q1 > p1) { p2 = (p1 > q2) ? p1 : q2; p1 = q1; }
            else if (q1 > p2) { p2 = q1; }
        }
        if (tx == 0) {
            size_t base = ((size_t)row * NCB + blockIdx.y) * 2;
            cand[base + 0] = p1;
            cand[base + 1] = p2;
        }
    }
}

// ---------------- refine: merge 64 candidates -> top-8, double-float rescore, argmax ---------
__global__ void refine8_kernel(const unsigned long long* __restrict__ cand,
                               const float* __restrict__ pe2p, const float* __restrict__ cpf,
                               const double* __restrict__ offd, int* __restrict__ gidx)
{
    int row  = blockIdx.x;                // 0..T-1
    int tid  = threadIdx.x;               // 256
    int lane = tid & 31, wid = tid >> 5;
    __shared__ int cidx[8];
    __shared__ double wsc[8];

    if (wid == 0) {
        unsigned long long v[2];
        const unsigned long long* pc = cand + (size_t)row * (NCB * 2);
        #pragma unroll
        for (int i = 0; i < 2; i++) v[i] = pc[lane + 32*i];
        #pragma unroll
        for (int r = 0; r < 8; r++) {
            unsigned long long m = v[0] > v[1] ? v[0] : v[1];
            #pragma unroll
            for (int off = 16; off; off >>= 1) {
                unsigned long long q = __shfl_xor_sync(0xffffffffu, m, off);
                if (q > m) m = q;
            }
            #pragma unroll
            for (int i = 0; i < 2; i++) if (v[i] == m) v[i] = 0ull;
            if (lane == 0) cidx[r] = KC - 1 - (int)(unsigned int)(m & 0xffffffffull);
        }
    }
    __syncthreads();

    int ci = cidx[wid];
    const float* crow = cpf + (size_t)ci * DMP;
    const float* prow = pe2p + (size_t)row * DMP;
    // compensated double-float dot (TwoProdFMA + TwoSum), ~1e-14 relative
    float hi = 0.f, lo = 0.f;
    for (int i = lane; i < DM; i += 32) {
        float a = prow[i], b = crow[i];
        float p = a * b;
        float perr = fmaf(a, b, -p);
        float s = hi + p;
        float z = s - hi;
        float serr = (hi - (s - z)) + (p - z);
        hi = s;
        lo += serr + perr;
    }
    double sd = (double)hi + (double)lo;
    #pragma unroll
    for (int off = 16; off; off >>= 1)
        sd += __shfl_xor_sync(0xffffffffu, sd, off);
    if (lane == 0) wsc[wid] = sd + offd[ci];
    __syncthreads();

    if (tid == 0) {
        double bs = wsc[0]; int bi = cidx[0];
        #pragma unroll
        for (int w = 1; w < 8; w++) {
            if (wsc[w] > bs || (wsc[w] == bs && cidx[w] < bi)) { bs = wsc[w]; bi = cidx[w]; }
        }
        gidx[row] = bi;
    }
}

// ---------------- gather: out[t,d] = table[idx_t, d] ----------------
__global__ void gather_kernel(const int* __restrict__ gidx,
                              const float* __restrict__ table, float* __restrict__ out)
{
    int idx = blockIdx.x * blockDim.x + threadIdx.x;
    if (idx >= NOUT) return;
    int t = idx / DM, d = idx % DM;
    int col = gidx[t];
    out[idx] = table[(size_t)col * DM + d];
}

// ---------------- host ----------------
extern "C" void kernel_launch(void* const* d_in, const int* in_sizes, int n_in,
                              void* d_out, int out_size)
{
    const float* x      = (const float*)d_in[0];
    const float* c1w    = (const float*)d_in[1];
    const float* c1b    = (const float*)d_in[2];
    const float* gn1s   = (const float*)d_in[3];
    const float* gn1b   = (const float*)d_in[4];
    const float* c2w    = (const float*)d_in[5];
    const float* c2b    = (const float*)d_in[6];
    const float* gn2s   = (const float*)d_in[7];
    const float* gn2b   = (const float*)d_in[8];
    const float* c3w    = (const float*)d_in[9];
    const float* c3b    = (const float*)d_in[10];
    const float* gn3s   = (const float*)d_in[11];
    const float* gn3b   = (const float*)d_in[12];
    const float* spec_w = (const float*)d_in[13];
    const float* spec_b = (const float*)d_in[14];
    const float* pos_w  = (const float*)d_in[15];
    const float* pos_b  = (const float*)d_in[16];
    const float* inp_w  = (const float*)d_in[17];
    const float* inp_b  = (const float*)d_in[18];
    const float* cb     = (const float*)d_in[19];
    const float* outp_w = (const float*)d_in[20];
    const float* outp_b = (const float*)d_in[21];
    float* out = (float*)d_out;

    float *pa, *pb, *ppe, *ppe2p, *pwT, *pcp, *poff, *ptable, *pstats;
    float *pct, *pst, *pmag, *pswp;
    double *poffd;
    unsigned long long* pcand;
    int* pidx;
    cudaGetSymbolAddress((void**)&pa,     g_a);
    cudaGetSymbolAddress((void**)&pb,     g_b);
    cudaGetSymbolAddress((void**)&ppe,    g_pe);
    cudaGetSymbolAddress((void**)&ppe2p,  g_pe2p);
    cudaGetSymbolAddress((void**)&pwT,    g_wT);
    cudaGetSymbolAddress((void**)&pcp,    g_cp);
    cudaGetSymbolAddress((void**)&poff,   g_off);
    cudaGetSymbolAddress((void**)&poffd,  g_offd);
    cudaGetSymbolAddress((void**)&ptable, g_table);
    cudaGetSymbolAddress((void**)&pstats, g_stats);
    cudaGetSymbolAddress((void**)&pct,    g_ct);
    cudaGetSymbolAddress((void**)&pst,    g_st);
    cudaGetSymbolAddress((void**)&pmag,   g_mag);
    cudaGetSymbolAddress((void**)&pswp,   g_swp);
    cudaGetSymbolAddress((void**)&pcand,  g_cand);
    cudaGetSymbolAddress((void**)&pidx,   g_idx);

    // side streams + events: created once on the (uncaptured) correctness call,
    // reused by the capture call. Work sequence is identical on every call.
    static cudaStream_t s_side = 0, s_spec = 0;
    static cudaEvent_t  s_fork = 0, s_join = 0, s_fork2 = 0, s_join2 = 0;
    if (s_side == 0) {
        cudaStreamCreateWithFlags(&s_side, cudaStreamNonBlocking);
        cudaStreamCreateWithFlags(&s_spec, cudaStreamNonBlocking);
        cudaEventCreateWithFlags(&s_fork,  cudaEventDisableTiming);
        cudaEventCreateWithFlags(&s_join,  cudaEventDisableTiming);
        cudaEventCreateWithFlags(&s_fork2, cudaEventDisableTiming);
        cudaEventCreateWithFlags(&s_join2, cudaEventDisableTiming);
    }

    // ---- fork 1: codebook branch on side stream (independent of encoder) ----
    cudaEventRecord(s_fork, 0);
    cudaStreamWaitEvent(s_side, s_fork, 0);
    transpose_w_kernel<<<(LLM*DM + 255)/256, 256, 0, s_side>>>(inp_w, pwT);
    {
        dim3 grid(KC/64, (DM + 63)/64);
        gemm_cb_kernel<<<grid, 256, 0, s_side>>>(cb, pwT, outp_w, outp_b, pcp, ptable);
    }
    off_kernel<<<KC, 256, 0, s_side>>>(cb, inp_b, poff, poffd);
    cudaEventRecord(s_join, s_side);

    // ---- fork 2: spectral pre-chain on its own stream (depends only on x) ----
    cudaEventRecord(s_fork2, 0);
    cudaStreamWaitEvent(s_spec, s_fork2, 0);
    trig_kernel<<<(101*PS + 255)/256, 256, 0, s_spec>>>(pct, pst);
    swpad_kernel<<<(DM*101 + 255)/256, 256, 0, s_spec>>>(spec_w, pswp);
    dft_kernel<<<T/64, 256, 0, s_spec>>>(x, pct, pst, pmag);
    cudaEventRecord(s_join2, s_spec);

    // ---- main: encoder chain (GN-apply fused into conv25f / specproj) ----
    conv1_kernel<<<T/8, 256>>>(x, c1w, c1b, pa);
    gn_stats_kernel<<<160, 256>>>(pa, pstats);
    {
        dim3 grid(15, BZ);
        conv25f_kernel<<<grid, 256>>>(pa, pstats, gn1s, gn1b, c2w, c2b, pb);
    }
    gn_stats_kernel<<<160, 256>>>(pb, pstats);
    {
        dim3 grid(15, BZ);
        conv25f_kernel<<<grid, 256>>>(pb, pstats, gn2s, gn2b, c3w, c3b, pa);
    }
    gn_stats_kernel<<<160, 256>>>(pa, pstats);

    // join spectral pre-chain, then fused projection
    cudaStreamWaitEvent(0, s_join2, 0);
    {
        dim3 grid(T/64, (DM + 63)/64);
        specproj_kernel<<<grid, 256>>>(pmag, pswp, spec_b, pa, pstats, gn3s, gn3b, ppe);
    }

    // smem-tiled positional conv (writes padded [TPAD x 208])
    {
        dim3 grid(25, BZ);
        posconv_kernel<<<grid, 256>>>(ppe, pos_w, pos_b, ppe2p);
    }

    // ---- join 1: score needs pcp/poff from side stream ----
    cudaStreamWaitEvent(0, s_join, 0);

    // score GEMM [TPAD x 4096], K=208, fused top-2 per 128-block
    {
        dim3 grid(TPAD/128, KC/128);
        score_kernel<<<grid, 256>>>(ppe2p, pcp, poff, pcand);
    }

    // exact decision: top-8 of 64 candidates, double-float rescore, argmax (tie -> smaller)
    refine8_kernel<<<T, 256>>>(pcand, ppe2p, pcp, poffd, pidx);

    // gather quantized output
    gather_kernel<<<(NOUT + 255)/256, 256>>>(pidx, ptable, out);
}